// round 6
// baseline (speedup 1.0000x reference)
#include <cuda_runtime.h>
#include <cuda_bf16.h>
#include <math.h>

// PMSN / S4D:  out[h,l] = Re( sum_n coeff_{h,n} * A_bar_{h,n}^l )
//
// R6: amortize setup. One block (256 thr) = 4 h-rows, 64 threads per h,
//   chain length 64. Conjugate-pair reduction (ACT=2 states per h, coeffs
//   doubled). Order-2 real recurrence per (thread, state):
//   u_{k+2} = p*u_{k+1} + q*u_k, p = 2 Re(W), q = -|W|^2, W = A_bar^64.
//   Seeds via 2-level smem power table (A_bar^(8j), A_bar^i).

#define NSTATE 4
#define ACT    2
#define TPB    256
#define HPB    4            // h-rows per block
#define TPH    64           // threads per h  -> chain stride

struct __align__(8) cfloat { float r, i; };

__device__ __forceinline__ cfloat cmul(cfloat a, cfloat b) {
    cfloat o;
    o.r = fmaf(a.r, b.r, -a.i * b.i);
    o.i = fmaf(a.r, b.i,  a.i * b.r);
    return o;
}

// exp((a + i b) * m) for small non-negative integer m (fp32 Cody-Waite).
__device__ __forceinline__ cfloat cexp_scaled(float a, float b, float m) {
    const float INV2PI = 0.15915494309189535f;
    const float C1     = 6.28125f;                  // exact in fp32
    const float C2     = 1.9353071795864764e-3f;    // 2*pi - C1
    float am = a * m;
    float bm = b * m;
    float k  = rintf(bm * INV2PI);
    float r  = fmaf(-k, C1, bm);
    r        = fmaf(-k, C2, r);
    float s, c;
    sincosf(r, &s, &c);
    float e = expf(am);
    cfloat o; o.r = e * c; o.i = e * s;
    return o;
}

__global__ __launch_bounds__(TPB, 6)
void pmsn_kernel(const float* __restrict__ log_dt,
                 const float* __restrict__ log_A_real,
                 const float* __restrict__ A_imag,
                 const float* __restrict__ VinvB_real,
                 const float* __restrict__ VinvB_imag,
                 const float* __restrict__ CV_real,
                 const float* __restrict__ CV_imag,
                 float* __restrict__ out,
                 int L)
{
    __shared__ cfloat sP8[HPB][ACT][8];    // A_bar^(8*j), j=0..7
    __shared__ cfloat sP1[HPB][ACT][8];    // A_bar^i,     i=0..7
    __shared__ cfloat sW[HPB][ACT];        // A_bar^64
    __shared__ cfloat sCoeff[HPB][ACT];    // 2 * C * B_bar

    const int tid   = threadIdx.x;
    const int grp   = tid >> 6;            // h-group within block
    const int t     = tid & 63;            // lane within h
    const int h     = blockIdx.x * HPB + grp;

    // ---- setup: 64 jobs per h (16 per state; 2 states active) ----
    {
        const int n   = t >> 4;            // state 0..3
        const int sub = t & 15;            // job within state
        const int base = h * NSTATE;
        const float myIm = A_imag[base + n];

        if (myIm > 0.0f) {
            // rank among positive-imag states of this h
            int slot = 0;
            #pragma unroll
            for (int m = 0; m < NSTATE; ++m)
                if (m < n && A_imag[base + m] > 0.0f) ++slot;

            const int idx = base + n;
            const float dt  = expf(log_dt[h]);
            const float Are = -expf(log_A_real[idx]);
            const float a = Are * dt;
            const float b = myIm * dt;

            if (sub < 7) {                          // sP8[1..7]
                sP8[grp][slot][sub + 1] = cexp_scaled(a, b, (float)(8 * (sub + 1)));
            } else if (sub < 14) {                  // sP1[1..7]
                sP1[grp][slot][sub - 6] = cexp_scaled(a, b, (float)(sub - 6));
            } else if (sub == 14) {                 // W = A_bar^64
                sW[grp][slot] = cexp_scaled(a, b, 64.0f);
            } else {                                // coeff + identities
                cfloat one; one.r = 1.0f; one.i = 0.0f;
                sP8[grp][slot][0] = one;
                sP1[grp][slot][0] = one;
                cfloat Ab = cexp_scaled(a, b, 1.0f);
                // B_bar = (A_bar - 1) * B / A ; coeff = 2 * C * B_bar
                const float Br = VinvB_real[idx], Bi = VinvB_imag[idx];
                const float t1r = (Ab.r - 1.0f) * Br - Ab.i * Bi;
                const float t1i = (Ab.r - 1.0f) * Bi + Ab.i * Br;
                const float invA = 1.0f / (Are * Are + myIm * myIm);
                const float Bbr = (t1r * Are + t1i * myIm) * invA;
                const float Bbi = (t1i * Are - t1r * myIm) * invA;
                const float Cr = CV_real[idx], Ci = CV_imag[idx];
                cfloat cf;
                cf.r = 2.0f * (Cr * Bbr - Ci * Bbi);
                cf.i = 2.0f * (Cr * Bbi + Ci * Bbr);
                sCoeff[grp][slot] = cf;
            }
        }
    }
    __syncthreads();

    // ---- seeds: z = coeff * A_bar^t via 2-level table ----
    float ua[ACT], ub[ACT], p[ACT], q[ACT];
    const int i1 = t & 7;
    const int j8 = t >> 3;

#pragma unroll
    for (int n = 0; n < ACT; ++n) {
        cfloat z = cmul(cmul(sCoeff[grp][n], sP8[grp][n][j8]), sP1[grp][n][i1]);
        const cfloat W = sW[grp][n];
        ua[n] = z.r;                          // Re at l = t
        ub[n] = z.r * W.r - z.i * W.i;        // Re at l = t + 64
        p[n]  = 2.0f * W.r;
        q[n]  = -fmaf(W.r, W.r, W.i * W.i);
    }

    // ---- main loop: 2 order-2 chains, stride TPH, coalesced stores ----
    float* rowp = out + (size_t)h * (size_t)L + t;

#pragma unroll 8
    for (int l = t; l < L; l += TPH) {
        *rowp = ua[0] + ua[1];
        rowp += TPH;
#pragma unroll
        for (int n = 0; n < ACT; ++n) {
            const float nxt = fmaf(p[n], ub[n], q[n] * ua[n]);
            ua[n] = ub[n];
            ub[n] = nxt;
        }
    }
}

extern "C" void kernel_launch(void* const* d_in, const int* in_sizes, int n_in,
                              void* d_out, int out_size)
{
    const float* log_dt     = (const float*)d_in[0];
    const float* log_A_real = (const float*)d_in[1];
    const float* A_imag     = (const float*)d_in[2];
    const float* VinvB_real = (const float*)d_in[3];
    const float* VinvB_imag = (const float*)d_in[4];
    const float* CV_real    = (const float*)d_in[5];
    const float* CV_imag    = (const float*)d_in[6];

    const int H = in_sizes[0];
    const int L = out_size / H;

    float* out = (float*)d_out;

    pmsn_kernel<<<H / HPB, TPB>>>(log_dt, log_A_real, A_imag,
                                  VinvB_real, VinvB_imag,
                                  CV_real, CV_imag, out, L);
}